// round 1
// baseline (speedup 1.0000x reference)
#include <cuda_runtime.h>
#include <math.h>

#define NB   4
#define SEQ  2048
#define NH   16
#define HD   64
#define DM   1024
#define TOK  (NB*SEQ)      /* 8192 tokens */

/* ---- scratch (device globals: allocation-free rule) ---- */
__device__ float g_q[(size_t)TOK*DM];
__device__ float g_k[(size_t)TOK*DM];
__device__ float g_v[(size_t)TOK*DM];
__device__ float g_att[(size_t)TOK*DM];
__device__ float g_invf[HD/2];

/* ================= inv_freq init (fp64, once per launch) ================= */
__global__ void init_invfreq_kernel() {
    int i = threadIdx.x;              /* 0..31 */
    if (i < HD/2) {
        double v = pow(10000.0, -(double)i / 32.0);
        g_invf[i] = (float)v;
    }
}

/* ================= GEMM: C[M,1024] = A[M,1024] @ W[1024,1024]^T + bias =================
   128x128 block tile, K-tile 16, 256 threads, 8x8 per thread. */
__global__ __launch_bounds__(256) void gemm_bias_kernel(
    const float* __restrict__ A, const float* __restrict__ W,
    const float* __restrict__ bias, float* __restrict__ C)
{
    const int K = DM;
    __shared__ __align__(16) float As[16][132];
    __shared__ __align__(16) float Ws[16][132];

    int bm = blockIdx.y * 128;
    int bn = blockIdx.x * 128;
    int tid = threadIdx.x;
    int tx = tid & 15, ty = tid >> 4;

    float acc[8][8];
#pragma unroll
    for (int i = 0; i < 8; ++i)
#pragma unroll
        for (int j = 0; j < 8; ++j) acc[i][j] = 0.f;

    for (int k0 = 0; k0 < K; k0 += 16) {
        /* load 128 rows x 16 k, as float4 along k; transpose into smem */
#pragma unroll
        for (int i = 0; i < 2; ++i) {
            int e = tid + i*256;       /* 0..511 */
            int r = e >> 2;            /* 0..127 */
            int c = e & 3;             /* float4 idx in k */
            float4 av = *(const float4*)&A[(size_t)(bm+r)*K + k0 + c*4];
            As[c*4+0][r] = av.x; As[c*4+1][r] = av.y;
            As[c*4+2][r] = av.z; As[c*4+3][r] = av.w;
            float4 wv = *(const float4*)&W[(size_t)(bn+r)*K + k0 + c*4];
            Ws[c*4+0][r] = wv.x; Ws[c*4+1][r] = wv.y;
            Ws[c*4+2][r] = wv.z; Ws[c*4+3][r] = wv.w;
        }
        __syncthreads();
#pragma unroll
        for (int kk = 0; kk < 16; ++kk) {
            float4 a0 = *(const float4*)&As[kk][ty*8];
            float4 a1 = *(const float4*)&As[kk][ty*8+4];
            float4 w0 = *(const float4*)&Ws[kk][tx*8];
            float4 w1 = *(const float4*)&Ws[kk][tx*8+4];
            float rm[8] = {a0.x,a0.y,a0.z,a0.w,a1.x,a1.y,a1.z,a1.w};
            float rn[8] = {w0.x,w0.y,w0.z,w0.w,w1.x,w1.y,w1.z,w1.w};
#pragma unroll
            for (int i = 0; i < 8; ++i)
#pragma unroll
                for (int j = 0; j < 8; ++j)
                    acc[i][j] += rm[i]*rn[j];
        }
        __syncthreads();
    }

#pragma unroll
    for (int i = 0; i < 8; ++i) {
        int m = bm + ty*8 + i;
#pragma unroll
        for (int j = 0; j < 8; ++j) {
            int n = bn + tx*8 + j;
            C[(size_t)m*DM + n] = acc[i][j] + bias[n];
        }
    }
}

/* ================= RoPE (in-place on q and k) ================= */
__global__ __launch_bounds__(256) void rope_kernel() {
    const int total = TOK * NH * (HD/2);   /* 4,194,304 per tensor */
    int idx = blockIdx.x * blockDim.x + threadIdx.x;
    if (idx >= 2*total) return;
    float* t = g_q;
    int i = idx;
    if (i >= total) { t = g_k; i -= total; }
    int pair  = i & 31;
    int rest  = i >> 5;       /* token*NH + h */
    int h     = rest & (NH-1);
    int token = rest >> 4;
    int n     = token & (SEQ-1);

    float invf = g_invf[pair];
    float ang  = (float)n * invf;
    float sv, cv;
    sincosf(ang, &sv, &cv);

    size_t off = (size_t)token*DM + h*HD + 2*pair;
    float2* p = (float2*)&t[off];
    float2 v = *p;
    float2 o;
    o.x = v.x*cv - v.y*sv;
    o.y = v.x*sv + v.y*cv;
    *p = o;
}

/* ================= Flash attention =================
   grid (SEQ/128, NH, NB), 128 threads; thread owns one query row. */
#define AQ 128
#define AK 64
#define ATTN_SMEM_BYTES ((2*AK*HD + AQ*(AK+1))*4)

__global__ __launch_bounds__(128) void attn_kernel() {
    extern __shared__ __align__(16) float sm[];
    float* Ks = sm;                 /* AK*HD */
    float* Vs = sm + AK*HD;         /* AK*HD */
    float* Ss = sm + 2*AK*HD;       /* AQ*(AK+1) */

    int tid = threadIdx.x;
    int q0  = blockIdx.x * AQ;
    int h   = blockIdx.y;
    int b   = blockIdx.z;
    const int rowStride = NH*HD;    /* 1024 */
    size_t base = (size_t)b*SEQ*rowStride + (size_t)h*HD;

    /* stage Q tile coalesced into sm, then pull own row into regs */
    for (int e = tid; e < AQ*HD; e += 128) {
        int r = e >> 6, d = e & 63;
        sm[e] = g_q[base + (size_t)(q0+r)*rowStride + d];
    }
    __syncthreads();
    float qreg[HD];
#pragma unroll
    for (int d4 = 0; d4 < 16; ++d4) {
        float4 qv = *(const float4*)&sm[tid*HD + d4*4];
        qreg[4*d4+0]=qv.x; qreg[4*d4+1]=qv.y; qreg[4*d4+2]=qv.z; qreg[4*d4+3]=qv.w;
    }

    float m_run = -1e30f, l_run = 0.f;
    float acc[HD];
#pragma unroll
    for (int d = 0; d < HD; ++d) acc[d] = 0.f;

    for (int kt = 0; kt < SEQ/AK; ++kt) {
        int k0 = kt*AK;
        __syncthreads();   /* prev-tile reads (and qreg staging) done */
        for (int e = tid; e < AK*HD; e += 128) {
            int r = e >> 6, d = e & 63;
            size_t goff = base + (size_t)(k0+r)*rowStride + d;
            Ks[e] = g_k[goff];
            Vs[e] = g_v[goff];
        }
        __syncthreads();

        /* scores for this tile -> Ss, track tile max */
        float mt = m_run;
#pragma unroll 4
        for (int j = 0; j < AK; ++j) {
            const float4* kr = (const float4*)(Ks + j*HD);
            float s0=0.f, s1=0.f, s2=0.f, s3=0.f;
#pragma unroll
            for (int d4 = 0; d4 < 16; ++d4) {
                float4 kv = kr[d4];
                s0 += qreg[4*d4+0]*kv.x;
                s1 += qreg[4*d4+1]*kv.y;
                s2 += qreg[4*d4+2]*kv.z;
                s3 += qreg[4*d4+3]*kv.w;
            }
            float s = ((s0+s1)+(s2+s3)) * 0.125f;   /* 1/sqrt(64) */
            Ss[tid*(AK+1) + j] = s;
            mt = fmaxf(mt, s);
        }

        float alpha = __expf(m_run - mt);
        l_run *= alpha;
#pragma unroll
        for (int d = 0; d < HD; ++d) acc[d] *= alpha;
        m_run = mt;

#pragma unroll 4
        for (int j = 0; j < AK; ++j) {
            float p = __expf(Ss[tid*(AK+1) + j] - mt);
            l_run += p;
            const float4* vr = (const float4*)(Vs + j*HD);
#pragma unroll
            for (int d4 = 0; d4 < 16; ++d4) {
                float4 vv = vr[d4];
                acc[4*d4+0] += p*vv.x;
                acc[4*d4+1] += p*vv.y;
                acc[4*d4+2] += p*vv.z;
                acc[4*d4+3] += p*vv.w;
            }
        }
    }

    float inv = 1.f / l_run;
    size_t obase = base + (size_t)(q0 + tid)*rowStride;
#pragma unroll
    for (int d4 = 0; d4 < 16; ++d4) {
        float4 o;
        o.x = acc[4*d4+0]*inv; o.y = acc[4*d4+1]*inv;
        o.z = acc[4*d4+2]*inv; o.w = acc[4*d4+3]*inv;
        *(float4*)&g_att[obase + d4*4] = o;
    }
}

/* ================= launch ================= */
extern "C" void kernel_launch(void* const* d_in, const int* in_sizes, int n_in,
                              void* d_out, int out_size)
{
    const float* x  = (const float*)d_in[0];
    const float* wq = (const float*)d_in[1];
    const float* bq = (const float*)d_in[2];
    const float* wk = (const float*)d_in[3];
    const float* bk = (const float*)d_in[4];
    const float* wv = (const float*)d_in[5];
    const float* bv = (const float*)d_in[6];
    const float* wo = (const float*)d_in[7];
    const float* bo = (const float*)d_in[8];
    float* out = (float*)d_out;

    float *gq, *gk, *gv, *ga;
    cudaGetSymbolAddress((void**)&gq, g_q);
    cudaGetSymbolAddress((void**)&gk, g_k);
    cudaGetSymbolAddress((void**)&gv, g_v);
    cudaGetSymbolAddress((void**)&ga, g_att);

    cudaFuncSetAttribute(attn_kernel,
                         cudaFuncAttributeMaxDynamicSharedMemorySize,
                         ATTN_SMEM_BYTES);

    init_invfreq_kernel<<<1, 32>>>();

    dim3 ggrid(DM/128, TOK/128);   /* (8, 64) */
    gemm_bias_kernel<<<ggrid, 256>>>(x, wq, bq, gq);
    gemm_bias_kernel<<<ggrid, 256>>>(x, wk, bk, gk);
    gemm_bias_kernel<<<ggrid, 256>>>(x, wv, bv, gv);

    int rope_threads = 2 * TOK * NH * (HD/2);
    rope_kernel<<<(rope_threads + 255)/256, 256>>>();

    dim3 agrid(SEQ/AQ, NH, NB);    /* (16, 16, 4) */
    attn_kernel<<<agrid, 128, ATTN_SMEM_BYTES>>>();

    gemm_bias_kernel<<<ggrid, 256>>>(ga, wo, bo, out);
}

// round 3
// speedup vs baseline: 1.2607x; 1.2607x over previous
#include <cuda_runtime.h>
#include <cuda_bf16.h>
#include <math.h>
#include <cstdint>

#define NB   4
#define SEQ  2048
#define NH   16
#define HD   64
#define DM   1024
#define TOK  (NB*SEQ)      /* 8192 tokens */

/* ---- scratch (device globals: allocation-free rule) ---- */
__device__ float g_q[(size_t)TOK*DM];
__device__ float g_k[(size_t)TOK*DM];
__device__ float g_v[(size_t)TOK*DM];
__device__ float g_att[(size_t)TOK*DM];
__device__ float g_invf[HD/2];

/* bf16 split operands (16B-aligned for cp.async) */
__device__ __align__(256) __nv_bfloat16 g_xh[(size_t)TOK*DM];
__device__ __align__(256) __nv_bfloat16 g_xl[(size_t)TOK*DM];
__device__ __align__(256) __nv_bfloat16 g_ah[(size_t)TOK*DM];
__device__ __align__(256) __nv_bfloat16 g_al[(size_t)TOK*DM];
__device__ __align__(256) __nv_bfloat16 g_wh[4][(size_t)DM*DM];
__device__ __align__(256) __nv_bfloat16 g_wl[4][(size_t)DM*DM];

/* ======================= PTX helpers (base sm_103 features only) ======================= */
__device__ __forceinline__ uint32_t smem_u32(const void* p) {
    uint32_t a;
    asm("{ .reg .u64 t; cvta.to.shared.u64 t, %1; cvt.u32.u64 %0, t; }" : "=r"(a) : "l"(p));
    return a;
}
#define CP_ASYNC16(dst, src) \
    asm volatile("cp.async.cg.shared.global [%0], [%1], 16;" :: "r"(dst), "l"(src) : "memory")
#define CP_COMMIT() asm volatile("cp.async.commit_group;" ::: "memory")
#define CP_WAIT1()  asm volatile("cp.async.wait_group 1;" ::: "memory")
#define CP_WAIT0()  asm volatile("cp.async.wait_group 0;" ::: "memory")

#define LDSM_X4(r, a) \
    asm volatile("ldmatrix.sync.aligned.m8n8.x4.shared.b16 {%0,%1,%2,%3}, [%4];" \
        : "=r"((r)[0]), "=r"((r)[1]), "=r"((r)[2]), "=r"((r)[3]) : "r"(a))
#define LDSM_X2(r, a) \
    asm volatile("ldmatrix.sync.aligned.m8n8.x2.shared.b16 {%0,%1}, [%2];" \
        : "=r"((r)[0]), "=r"((r)[1]) : "r"(a))

#define MMA16816(c, a, b) \
    asm volatile("mma.sync.aligned.m16n8k16.row.col.f32.bf16.bf16.f32 " \
        "{%0,%1,%2,%3},{%4,%5,%6,%7},{%8,%9},{%0,%1,%2,%3};" \
        : "+f"((c)[0]), "+f"((c)[1]), "+f"((c)[2]), "+f"((c)[3]) \
        : "r"((a)[0]), "r"((a)[1]), "r"((a)[2]), "r"((a)[3]), "r"((b)[0]), "r"((b)[1]))

/* ================= inv_freq init ================= */
__global__ void init_invfreq_kernel() {
    int i = threadIdx.x;
    if (i < HD/2) {
        double v = pow(10000.0, -(double)i / 32.0);
        g_invf[i] = (float)v;
    }
}

/* ================= fp32 -> bf16 hi/lo split ================= */
__global__ __launch_bounds__(256) void cvt_split_kernel(
    const float* __restrict__ src, __nv_bfloat16* __restrict__ hi,
    __nv_bfloat16* __restrict__ lo, int n4)
{
    int i = blockIdx.x * 256 + threadIdx.x;
    if (i >= n4) return;
    float4 v = ((const float4*)src)[i];
    __nv_bfloat16 h0 = __float2bfloat16_rn(v.x);
    __nv_bfloat16 h1 = __float2bfloat16_rn(v.y);
    __nv_bfloat16 h2 = __float2bfloat16_rn(v.z);
    __nv_bfloat16 h3 = __float2bfloat16_rn(v.w);
    __nv_bfloat16 l0 = __float2bfloat16_rn(v.x - __bfloat162float(h0));
    __nv_bfloat16 l1 = __float2bfloat16_rn(v.y - __bfloat162float(h1));
    __nv_bfloat16 l2 = __float2bfloat16_rn(v.z - __bfloat162float(h2));
    __nv_bfloat16 l3 = __float2bfloat16_rn(v.w - __bfloat162float(h3));
    __nv_bfloat162 hp0; hp0.x = h0; hp0.y = h1;
    __nv_bfloat162 hp1; hp1.x = h2; hp1.y = h3;
    __nv_bfloat162 lp0; lp0.x = l0; lp0.y = l1;
    __nv_bfloat162 lp1; lp1.x = l2; lp1.y = l3;
    uint2 hv = make_uint2(*(uint32_t*)&hp0, *(uint32_t*)&hp1);
    uint2 lv = make_uint2(*(uint32_t*)&lp0, *(uint32_t*)&lp1);
    ((uint2*)hi)[i] = hv;
    ((uint2*)lo)[i] = lv;
}

/* ================= mma.sync split-bf16 GEMM =================
   C[8192,1024] = A @ W^T + bias.  A,W as bf16 hi/lo pairs (K-major, [row][k]).
   CTA tile 128x128, 8 warps (2m x 4n), warp tile 64x32.
   K-stage 32, double-buffered cp.async. 3 passes: AhWh + AhWl + AlWh. */
#define KT      32
#define SROW    40                       /* padded smem row stride (elems) */
#define TILE_B  (128*SROW*2)             /* 10240 B per tile */
#define STAGE_B (4*TILE_B)               /* Ah, Al, Wh, Wl */
#define GEMM_SMEM (2*STAGE_B)            /* 81920 B */
#define NSTAGE  (DM/KT)                  /* 32 */

__device__ __forceinline__ void stage_loads(
    uint32_t sb, const __nv_bfloat16* __restrict__ Ah,
    const __nv_bfloat16* __restrict__ Al,
    const __nv_bfloat16* __restrict__ Wh,
    const __nv_bfloat16* __restrict__ Wl,
    int bm, int bn, int k0, int tid)
{
    const __nv_bfloat16* srcs[4] = {Ah, Al, Wh, Wl};
    int row0s[4] = {bm, bm, bn, bn};
    int r = tid >> 2, seg = tid & 3;     /* r: 0..63, seg: 0..3 */
#pragma unroll
    for (int t = 0; t < 4; ++t) {
        const __nv_bfloat16* src = srcs[t];
        int row0 = row0s[t];
#pragma unroll
        for (int half = 0; half < 2; ++half) {
            int row = half * 64 + r;
            uint32_t d = sb + t*TILE_B + row*(SROW*2) + seg*16;
            const void* g = src + (size_t)(row0 + row)*DM + k0 + seg*8;
            CP_ASYNC16(d, g);
        }
    }
}

__global__ __launch_bounds__(256)
void gemm_tc_kernel(const __nv_bfloat16* __restrict__ Ah,
                    const __nv_bfloat16* __restrict__ Al,
                    const __nv_bfloat16* __restrict__ Wh,
                    const __nv_bfloat16* __restrict__ Wl,
                    const float* __restrict__ bias,
                    float* __restrict__ C)
{
    extern __shared__ __align__(128) char smem[];
    uint32_t sbase = smem_u32(smem);
    int tid = threadIdx.x;
    int l   = tid & 31;
    int wid = tid >> 5;
    int wm  = wid & 1;        /* 2 m-warps */
    int wn  = wid >> 1;       /* 4 n-warps */
    int bm  = blockIdx.y * 128;
    int bn  = blockIdx.x * 128;

    float acc[4][4][4];
#pragma unroll
    for (int i = 0; i < 4; ++i)
#pragma unroll
        for (int j = 0; j < 4; ++j)
#pragma unroll
            for (int r = 0; r < 4; ++r) acc[i][j][r] = 0.f;

    /* ldmatrix per-thread base offsets */
    int rowA = wm*64 + (l & 15);
    int kA   = (l >> 4) * 8;             /* 0 or 8 */
    int rowB = wn*32 + (l & 7);
    int kB   = ((l >> 3) & 1) * 8;

    stage_loads(sbase,           Ah, Al, Wh, Wl, bm, bn, 0,  tid); CP_COMMIT();
    stage_loads(sbase + STAGE_B, Ah, Al, Wh, Wl, bm, bn, KT, tid); CP_COMMIT();

    for (int s = 0; s < NSTAGE; ++s) {
        CP_WAIT1();
        __syncthreads();
        uint32_t sb = sbase + (uint32_t)(s & 1) * STAGE_B;

#pragma unroll
        for (int kk = 0; kk < 2; ++kk) {
            int kb = kk * 16;
            uint32_t ah[4][4], al[4][4], wh[4][2], wl[4][2];
#pragma unroll
            for (int i = 0; i < 4; ++i) {
                uint32_t ao = sb + (uint32_t)((rowA + i*16)*(SROW*2) + (kb + kA)*2);
                LDSM_X4(ah[i], ao + 0*TILE_B);
                LDSM_X4(al[i], ao + 1*TILE_B);
            }
#pragma unroll
            for (int j = 0; j < 4; ++j) {
                uint32_t bo = sb + (uint32_t)((rowB + j*8)*(SROW*2) + (kb + kB)*2);
                LDSM_X2(wh[j], bo + 2*TILE_B);
                LDSM_X2(wl[j], bo + 3*TILE_B);
            }
#pragma unroll
            for (int i = 0; i < 4; ++i)
#pragma unroll
                for (int j = 0; j < 4; ++j) {
                    MMA16816(acc[i][j], ah[i], wh[j]);
                    MMA16816(acc[i][j], ah[i], wl[j]);
                    MMA16816(acc[i][j], al[i], wh[j]);
                }
        }
        __syncthreads();
        if (s + 2 < NSTAGE)
            stage_loads(sbase + (uint32_t)(s & 1)*STAGE_B, Ah, Al, Wh, Wl,
                        bm, bn, (s + 2)*KT, tid);
        CP_COMMIT();
    }

    /* epilogue: add bias, store fp32 */
    int g   = l >> 2, tig = l & 3;
#pragma unroll
    for (int i = 0; i < 4; ++i) {
        int row = bm + wm*64 + i*16 + g;
#pragma unroll
        for (int j = 0; j < 4; ++j) {
            int col = bn + wn*32 + j*8 + tig*2;
            float2 bv = *(const float2*)&bias[col];
            float2 o0, o1;
            o0.x = acc[i][j][0] + bv.x;  o0.y = acc[i][j][1] + bv.y;
            o1.x = acc[i][j][2] + bv.x;  o1.y = acc[i][j][3] + bv.y;
            *(float2*)&C[(size_t)row*DM + col]       = o0;
            *(float2*)&C[(size_t)(row+8)*DM + col]   = o1;
        }
    }
}

/* ================= RoPE (in-place on q and k) ================= */
__global__ __launch_bounds__(256) void rope_kernel() {
    const int total = TOK * NH * (HD/2);
    int idx = blockIdx.x * blockDim.x + threadIdx.x;
    if (idx >= 2*total) return;
    float* t = g_q;
    int i = idx;
    if (i >= total) { t = g_k; i -= total; }
    int pair  = i & 31;
    int rest  = i >> 5;
    int h     = rest & (NH-1);
    int token = rest >> 4;
    int n     = token & (SEQ-1);

    float invf = g_invf[pair];
    float ang  = (float)n * invf;
    float sv, cv;
    sincosf(ang, &sv, &cv);

    size_t off = (size_t)token*DM + h*HD + 2*pair;
    float2* p = (float2*)&t[off];
    float2 v = *p;
    float2 o;
    o.x = v.x*cv - v.y*sv;
    o.y = v.x*sv + v.y*cv;
    *p = o;
}

/* ================= Flash attention (SIMT fp32, unchanged) ================= */
#define AQ 128
#define AK 64
#define ATTN_SMEM_BYTES ((2*AK*HD + AQ*(AK+1))*4)

__global__ __launch_bounds__(128) void attn_kernel() {
    extern __shared__ __align__(16) float sm[];
    float* Ks = sm;
    float* Vs = sm + AK*HD;
    float* Ss = sm + 2*AK*HD;

    int tid = threadIdx.x;
    int q0  = blockIdx.x * AQ;
    int h   = blockIdx.y;
    int b   = blockIdx.z;
    const int rowStride = NH*HD;
    size_t base = (size_t)b*SEQ*rowStride + (size_t)h*HD;

    for (int e = tid; e < AQ*HD; e += 128) {
        int r = e >> 6, d = e & 63;
        sm[e] = g_q[base + (size_t)(q0+r)*rowStride + d];
    }
    __syncthreads();
    float qreg[HD];
#pragma unroll
    for (int d4 = 0; d4 < 16; ++d4) {
        float4 qv = *(const float4*)&sm[tid*HD + d4*4];
        qreg[4*d4+0]=qv.x; qreg[4*d4+1]=qv.y; qreg[4*d4+2]=qv.z; qreg[4*d4+3]=qv.w;
    }

    float m_run = -1e30f, l_run = 0.f;
    float acc[HD];
#pragma unroll
    for (int d = 0; d < HD; ++d) acc[d] = 0.f;

    for (int kt = 0; kt < SEQ/AK; ++kt) {
        int k0 = kt*AK;
        __syncthreads();
        for (int e = tid; e < AK*HD; e += 128) {
            int r = e >> 6, d = e & 63;
            size_t goff = base + (size_t)(k0+r)*rowStride + d;
            Ks[e] = g_k[goff];
            Vs[e] = g_v[goff];
        }
        __syncthreads();

        float mt = m_run;
#pragma unroll 4
        for (int j = 0; j < AK; ++j) {
            const float4* kr = (const float4*)(Ks + j*HD);
            float s0=0.f, s1=0.f, s2=0.f, s3=0.f;
#pragma unroll
            for (int d4 = 0; d4 < 16; ++d4) {
                float4 kv = kr[d4];
                s0 += qreg[4*d4+0]*kv.x;
                s1 += qreg[4*d4+1]*kv.y;
                s2 += qreg[4*d4+2]*kv.z;
                s3 += qreg[4*d4+3]*kv.w;
            }
            float s = ((s0+s1)+(s2+s3)) * 0.125f;
            Ss[tid*(AK+1) + j] = s;
            mt = fmaxf(mt, s);
        }

        float alpha = __expf(m_run - mt);
        l_run *= alpha;
#pragma unroll
        for (int d = 0; d < HD; ++d) acc[d] *= alpha;
        m_run = mt;

#pragma unroll 4
        for (int j = 0; j < AK; ++j) {
            float p = __expf(Ss[tid*(AK+1) + j] - mt);
            l_run += p;
            const float4* vr = (const float4*)(Vs + j*HD);
#pragma unroll
            for (int d4 = 0; d4 < 16; ++d4) {
                float4 vv = vr[d4];
                acc[4*d4+0] += p*vv.x;
                acc[4*d4+1] += p*vv.y;
                acc[4*d4+2] += p*vv.z;
                acc[4*d4+3] += p*vv.w;
            }
        }
    }

    float inv = 1.f / l_run;
    size_t obase = base + (size_t)(q0 + tid)*rowStride;
#pragma unroll
    for (int d4 = 0; d4 < 16; ++d4) {
        float4 o;
        o.x = acc[4*d4+0]*inv; o.y = acc[4*d4+1]*inv;
        o.z = acc[4*d4+2]*inv; o.w = acc[4*d4+3]*inv;
        *(float4*)&g_att[obase + d4*4] = o;
    }
}

/* ================= launch ================= */
extern "C" void kernel_launch(void* const* d_in, const int* in_sizes, int n_in,
                              void* d_out, int out_size)
{
    const float* x  = (const float*)d_in[0];
    const float* wq = (const float*)d_in[1];
    const float* bq = (const float*)d_in[2];
    const float* wk = (const float*)d_in[3];
    const float* bk = (const float*)d_in[4];
    const float* wv = (const float*)d_in[5];
    const float* bv = (const float*)d_in[6];
    const float* wo = (const float*)d_in[7];
    const float* bo = (const float*)d_in[8];
    float* out = (float*)d_out;

    float *gq, *gk, *gv, *ga;
    cudaGetSymbolAddress((void**)&gq, g_q);
    cudaGetSymbolAddress((void**)&gk, g_k);
    cudaGetSymbolAddress((void**)&gv, g_v);
    cudaGetSymbolAddress((void**)&ga, g_att);
    __nv_bfloat16 *xh, *xl, *ah, *al, *wh, *wl;
    cudaGetSymbolAddress((void**)&xh, g_xh);
    cudaGetSymbolAddress((void**)&xl, g_xl);
    cudaGetSymbolAddress((void**)&ah, g_ah);
    cudaGetSymbolAddress((void**)&al, g_al);
    cudaGetSymbolAddress((void**)&wh, g_wh);
    cudaGetSymbolAddress((void**)&wl, g_wl);

    cudaFuncSetAttribute(attn_kernel, cudaFuncAttributeMaxDynamicSharedMemorySize,
                         ATTN_SMEM_BYTES);
    cudaFuncSetAttribute(gemm_tc_kernel, cudaFuncAttributeMaxDynamicSharedMemorySize,
                         GEMM_SMEM);

    init_invfreq_kernel<<<1, 32>>>();

    const int n4x = TOK*DM/4;
    const int n4w = DM*DM/4;
    cvt_split_kernel<<<(n4x+255)/256, 256>>>(x,  xh, xl, n4x);
    cvt_split_kernel<<<(n4w+255)/256, 256>>>(wq, wh + 0*(size_t)DM*DM, wl + 0*(size_t)DM*DM, n4w);
    cvt_split_kernel<<<(n4w+255)/256, 256>>>(wk, wh + 1*(size_t)DM*DM, wl + 1*(size_t)DM*DM, n4w);
    cvt_split_kernel<<<(n4w+255)/256, 256>>>(wv, wh + 2*(size_t)DM*DM, wl + 2*(size_t)DM*DM, n4w);
    cvt_split_kernel<<<(n4w+255)/256, 256>>>(wo, wh + 3*(size_t)DM*DM, wl + 3*(size_t)DM*DM, n4w);

    dim3 ggrid(DM/128, TOK/128);    /* (8, 64) */
    gemm_tc_kernel<<<ggrid, 256, GEMM_SMEM>>>(xh, xl, wh + 0*(size_t)DM*DM, wl + 0*(size_t)DM*DM, bq, gq);
    gemm_tc_kernel<<<ggrid, 256, GEMM_SMEM>>>(xh, xl, wh + 1*(size_t)DM*DM, wl + 1*(size_t)DM*DM, bk, gk);
    gemm_tc_kernel<<<ggrid, 256, GEMM_SMEM>>>(xh, xl, wh + 2*(size_t)DM*DM, wl + 2*(size_t)DM*DM, bv, gv);

    int rope_threads = 2 * TOK * NH * (HD/2);
    rope_kernel<<<(rope_threads + 255)/256, 256>>>();

    dim3 agrid(SEQ/AQ, NH, NB);
    attn_kernel<<<agrid, 128, ATTN_SMEM_BYTES>>>();

    cvt_split_kernel<<<(n4x+255)/256, 256>>>(ga, ah, al, n4x);
    gemm_tc_kernel<<<ggrid, 256, GEMM_SMEM>>>(ah, al, wh + 3*(size_t)DM*DM, wl + 3*(size_t)DM*DM, bo, out);
}

// round 4
// speedup vs baseline: 3.2949x; 2.6136x over previous
#include <cuda_runtime.h>
#include <cuda_bf16.h>
#include <math.h>
#include <cstdint>

#define NB   4
#define SEQ  2048
#define NH   16
#define HD   64
#define DM   1024
#define TOK  (NB*SEQ)      /* 8192 tokens */

/* ---- scratch (device globals: allocation-free rule) ---- */
__device__ float g_q[(size_t)TOK*DM];
__device__ float g_k[(size_t)TOK*DM];
__device__ float g_v[(size_t)TOK*DM];
__device__ float g_att[(size_t)TOK*DM];
__device__ float g_invf[HD/2];

/* bf16 split operands (16B-aligned for cp.async) */
__device__ __align__(256) __nv_bfloat16 g_xh[(size_t)TOK*DM];
__device__ __align__(256) __nv_bfloat16 g_xl[(size_t)TOK*DM];
__device__ __align__(256) __nv_bfloat16 g_ah[(size_t)TOK*DM];
__device__ __align__(256) __nv_bfloat16 g_al[(size_t)TOK*DM];
__device__ __align__(256) __nv_bfloat16 g_vh[(size_t)TOK*DM];
__device__ __align__(256) __nv_bfloat16 g_vl[(size_t)TOK*DM];
__device__ __align__(256) __nv_bfloat16 g_wh[4][(size_t)DM*DM];
__device__ __align__(256) __nv_bfloat16 g_wl[4][(size_t)DM*DM];

/* ======================= PTX helpers (base sm_103 features only) ======================= */
__device__ __forceinline__ uint32_t smem_u32(const void* p) {
    uint32_t a;
    asm("{ .reg .u64 t; cvta.to.shared.u64 t, %1; cvt.u32.u64 %0, t; }" : "=r"(a) : "l"(p));
    return a;
}
#define CP_ASYNC16(dst, src) \
    asm volatile("cp.async.cg.shared.global [%0], [%1], 16;" :: "r"(dst), "l"(src) : "memory")
#define CP_COMMIT() asm volatile("cp.async.commit_group;" ::: "memory")
#define CP_WAIT1()  asm volatile("cp.async.wait_group 1;" ::: "memory")

#define LDSM_X4(r, a) \
    asm volatile("ldmatrix.sync.aligned.m8n8.x4.shared.b16 {%0,%1,%2,%3}, [%4];" \
        : "=r"((r)[0]), "=r"((r)[1]), "=r"((r)[2]), "=r"((r)[3]) : "r"(a))
#define LDSM_X2(r, a) \
    asm volatile("ldmatrix.sync.aligned.m8n8.x2.shared.b16 {%0,%1}, [%2];" \
        : "=r"((r)[0]), "=r"((r)[1]) : "r"(a))
#define LDSM_X4T(r, a) \
    asm volatile("ldmatrix.sync.aligned.m8n8.x4.trans.shared.b16 {%0,%1,%2,%3}, [%4];" \
        : "=r"((r)[0]), "=r"((r)[1]), "=r"((r)[2]), "=r"((r)[3]) : "r"(a))

#define MMA16816(c, a, b) \
    asm volatile("mma.sync.aligned.m16n8k16.row.col.f32.bf16.bf16.f32 " \
        "{%0,%1,%2,%3},{%4,%5,%6,%7},{%8,%9},{%0,%1,%2,%3};" \
        : "+f"((c)[0]), "+f"((c)[1]), "+f"((c)[2]), "+f"((c)[3]) \
        : "r"((a)[0]), "r"((a)[1]), "r"((a)[2]), "r"((a)[3]), "r"((b)[0]), "r"((b)[1]))

__device__ __forceinline__ void split2(float f0, float f1, uint32_t& h, uint32_t& lo) {
    __nv_bfloat162 hh = __floats2bfloat162_rn(f0, f1);
    float g0 = __bfloat162float(hh.x);
    float g1 = __bfloat162float(hh.y);
    __nv_bfloat162 ll = __floats2bfloat162_rn(f0 - g0, f1 - g1);
    h  = *(uint32_t*)&hh;
    lo = *(uint32_t*)&ll;
}

/* ================= inv_freq init ================= */
__global__ void init_invfreq_kernel() {
    int i = threadIdx.x;
    if (i < HD/2) {
        double v = pow(10000.0, -(double)i / 32.0);
        g_invf[i] = (float)v;
    }
}

/* ================= fp32 -> bf16 hi/lo split (with scale) ================= */
__global__ __launch_bounds__(256) void cvt_split_kernel(
    const float* __restrict__ src, __nv_bfloat16* __restrict__ hi,
    __nv_bfloat16* __restrict__ lo, int n4, float scale)
{
    int i = blockIdx.x * 256 + threadIdx.x;
    if (i >= n4) return;
    float4 v = ((const float4*)src)[i];
    v.x *= scale; v.y *= scale; v.z *= scale; v.w *= scale;
    uint32_t h0, l0, h1, l1;
    split2(v.x, v.y, h0, l0);
    split2(v.z, v.w, h1, l1);
    ((uint2*)hi)[i] = make_uint2(h0, h1);
    ((uint2*)lo)[i] = make_uint2(l0, l1);
}

/* ================= mma.sync split-bf16 GEMM (unchanged from R3) ================= */
#define KT      32
#define SROW    40
#define TILE_B  (128*SROW*2)
#define STAGE_B (4*TILE_B)
#define GEMM_SMEM (2*STAGE_B)
#define NSTAGE  (DM/KT)

__device__ __forceinline__ void stage_loads(
    uint32_t sb, const __nv_bfloat16* __restrict__ Ah,
    const __nv_bfloat16* __restrict__ Al,
    const __nv_bfloat16* __restrict__ Wh,
    const __nv_bfloat16* __restrict__ Wl,
    int bm, int bn, int k0, int tid)
{
    const __nv_bfloat16* srcs[4] = {Ah, Al, Wh, Wl};
    int row0s[4] = {bm, bm, bn, bn};
    int r = tid >> 2, seg = tid & 3;
#pragma unroll
    for (int t = 0; t < 4; ++t) {
        const __nv_bfloat16* src = srcs[t];
        int row0 = row0s[t];
#pragma unroll
        for (int half = 0; half < 2; ++half) {
            int row = half * 64 + r;
            uint32_t d = sb + t*TILE_B + row*(SROW*2) + seg*16;
            const void* g = src + (size_t)(row0 + row)*DM + k0 + seg*8;
            CP_ASYNC16(d, g);
        }
    }
}

__global__ __launch_bounds__(256)
void gemm_tc_kernel(const __nv_bfloat16* __restrict__ Ah,
                    const __nv_bfloat16* __restrict__ Al,
                    const __nv_bfloat16* __restrict__ Wh,
                    const __nv_bfloat16* __restrict__ Wl,
                    const float* __restrict__ bias,
                    float* __restrict__ C)
{
    extern __shared__ __align__(128) char smem[];
    uint32_t sbase = smem_u32(smem);
    int tid = threadIdx.x;
    int l   = tid & 31;
    int wid = tid >> 5;
    int wm  = wid & 1;
    int wn  = wid >> 1;
    int bm  = blockIdx.y * 128;
    int bn  = blockIdx.x * 128;

    float acc[4][4][4];
#pragma unroll
    for (int i = 0; i < 4; ++i)
#pragma unroll
        for (int j = 0; j < 4; ++j)
#pragma unroll
            for (int r = 0; r < 4; ++r) acc[i][j][r] = 0.f;

    int rowA = wm*64 + (l & 15);
    int kA   = (l >> 4) * 8;
    int rowB = wn*32 + (l & 7);
    int kB   = ((l >> 3) & 1) * 8;

    stage_loads(sbase,           Ah, Al, Wh, Wl, bm, bn, 0,  tid); CP_COMMIT();
    stage_loads(sbase + STAGE_B, Ah, Al, Wh, Wl, bm, bn, KT, tid); CP_COMMIT();

    for (int s = 0; s < NSTAGE; ++s) {
        CP_WAIT1();
        __syncthreads();
        uint32_t sb = sbase + (uint32_t)(s & 1) * STAGE_B;

#pragma unroll
        for (int kk = 0; kk < 2; ++kk) {
            int kb = kk * 16;
            uint32_t ah[4][4], al[4][4], wh[4][2], wl[4][2];
#pragma unroll
            for (int i = 0; i < 4; ++i) {
                uint32_t ao = sb + (uint32_t)((rowA + i*16)*(SROW*2) + (kb + kA)*2);
                LDSM_X4(ah[i], ao + 0*TILE_B);
                LDSM_X4(al[i], ao + 1*TILE_B);
            }
#pragma unroll
            for (int j = 0; j < 4; ++j) {
                uint32_t bo = sb + (uint32_t)((rowB + j*8)*(SROW*2) + (kb + kB)*2);
                LDSM_X2(wh[j], bo + 2*TILE_B);
                LDSM_X2(wl[j], bo + 3*TILE_B);
            }
#pragma unroll
            for (int i = 0; i < 4; ++i)
#pragma unroll
                for (int j = 0; j < 4; ++j) {
                    MMA16816(acc[i][j], ah[i], wh[j]);
                    MMA16816(acc[i][j], ah[i], wl[j]);
                    MMA16816(acc[i][j], al[i], wh[j]);
                }
        }
        __syncthreads();
        if (s + 2 < NSTAGE)
            stage_loads(sbase + (uint32_t)(s & 1)*STAGE_B, Ah, Al, Wh, Wl,
                        bm, bn, (s + 2)*KT, tid);
        CP_COMMIT();
    }

    int g   = l >> 2, tig = l & 3;
#pragma unroll
    for (int i = 0; i < 4; ++i) {
        int row = bm + wm*64 + i*16 + g;
#pragma unroll
        for (int j = 0; j < 4; ++j) {
            int col = bn + wn*32 + j*8 + tig*2;
            float2 bv = *(const float2*)&bias[col];
            float2 o0, o1;
            o0.x = acc[i][j][0] + bv.x;  o0.y = acc[i][j][1] + bv.y;
            o1.x = acc[i][j][2] + bv.x;  o1.y = acc[i][j][3] + bv.y;
            *(float2*)&C[(size_t)row*DM + col]       = o0;
            *(float2*)&C[(size_t)(row+8)*DM + col]   = o1;
        }
    }
}

/* ================= RoPE (in-place on q and k) ================= */
__global__ __launch_bounds__(256) void rope_kernel() {
    const int total = TOK * NH * (HD/2);
    int idx = blockIdx.x * blockDim.x + threadIdx.x;
    if (idx >= 2*total) return;
    float* t = g_q;
    int i = idx;
    if (i >= total) { t = g_k; i -= total; }
    int pair  = i & 31;
    int rest  = i >> 5;
    int h     = rest & (NH-1);
    int token = rest >> 4;
    int n     = token & (SEQ-1);

    float invf = g_invf[pair];
    float ang  = (float)n * invf;
    float sv, cv;
    sincosf(ang, &sv, &cv);

    size_t off = (size_t)token*DM + h*HD + 2*pair;
    float2* p = (float2*)&t[off];
    float2 v = *p;
    float2 o;
    o.x = v.x*cv - v.y*sv;
    o.y = v.x*sv + v.y*cv;
    *p = o;
}

/* ================= Tensor-core flash attention =================
   grid (SEQ/128, NH, NB), 256 threads = 8 warps; warp owns 16 q-rows.
   K/V chunks of 64 keys, split bf16 (h/l), double-buffered cp.async.
   Scores: QhKh+QhKl+QlKh.  PV: PhVh+PhVl+PlVh. */
#define ACH   64                         /* keys per chunk */
#define VSTR  72                         /* smem row stride, elems */
#define VSTRB (VSTR*2)                   /* 144 B */
#define ATILE (ACH*VSTRB)                /* 9216 B */
#define ASTG  (4*ATILE)                  /* Kh,Kl,Vh,Vl */
#define ATTN_SMEM (2*ASTG)               /* 73728 B */
#define NCH   (SEQ/ACH)                  /* 32 */

__device__ __forceinline__ void attn_stage(
    uint32_t sb, const __nv_bfloat16* kh, const __nv_bfloat16* kl,
    const __nv_bfloat16* vh, const __nv_bfloat16* vl,
    size_t gbase, int k0, int tid)
{
    const __nv_bfloat16* srcs[4] = {kh, kl, vh, vl};
#pragma unroll
    for (int u = tid; u < 2048; u += 256) {
        int t   = u >> 9;
        int row = (u >> 3) & 63;
        int seg = u & 7;
        uint32_t d = sb + t*ATILE + row*VSTRB + seg*16;
        const void* g = srcs[t] + gbase + (size_t)(k0 + row)*DM + seg*8;
        CP_ASYNC16(d, g);
    }
}

__global__ __launch_bounds__(256)
void attn_tc_kernel(const __nv_bfloat16* __restrict__ qh,
                    const __nv_bfloat16* __restrict__ ql,
                    const __nv_bfloat16* __restrict__ kh,
                    const __nv_bfloat16* __restrict__ kl,
                    const __nv_bfloat16* __restrict__ vh,
                    const __nv_bfloat16* __restrict__ vl)
{
    extern __shared__ __align__(128) char smem[];
    uint32_t sbase = smem_u32(smem);
    int tid = threadIdx.x;
    int l   = tid & 31;
    int w   = tid >> 5;                  /* 8 warps */
    int q0  = blockIdx.x * 128;
    int h   = blockIdx.y;
    int b   = blockIdx.z;

    size_t gbase = (size_t)b*SEQ*DM + (size_t)h*HD;   /* token-row base */

    /* ---- preload Q fragments (scaled by 1/8 at conversion) ---- */
    int qrow = q0 + w*16 + (l >> 2);
    int qcol = (l & 3) * 2;
    uint32_t qhf[4][4], qlf[4][4];
#pragma unroll
    for (int kk = 0; kk < 4; ++kk) {
        size_t o00 = gbase + (size_t)qrow*DM + kk*16 + qcol;
        qhf[kk][0] = *(const uint32_t*)(qh + o00);
        qhf[kk][1] = *(const uint32_t*)(qh + o00 + 8*DM);
        qhf[kk][2] = *(const uint32_t*)(qh + o00 + 8);
        qhf[kk][3] = *(const uint32_t*)(qh + o00 + 8*DM + 8);
        qlf[kk][0] = *(const uint32_t*)(ql + o00);
        qlf[kk][1] = *(const uint32_t*)(ql + o00 + 8*DM);
        qlf[kk][2] = *(const uint32_t*)(ql + o00 + 8);
        qlf[kk][3] = *(const uint32_t*)(ql + o00 + 8*DM + 8);
    }

    float oacc[8][4];
#pragma unroll
    for (int j = 0; j < 8; ++j)
#pragma unroll
        for (int r = 0; r < 4; ++r) oacc[j][r] = 0.f;
    float mA = -1e30f, mB = -1e30f, lA = 0.f, lB = 0.f;

    /* ldmatrix per-thread smem offsets (within a tile) */
    /* K (non-trans x4): mats [b0_j, b1_j, b0_j+1, b1_j+1] */
    uint32_t kKey = ((l >> 4) & 1) * 8 + (l & 7);
    uint32_t kDim = ((l >> 3) & 1) * 8;
    /* V (trans x4): mats [dim-tile 2jp (b0,b1), dim-tile 2jp+1] */
    uint32_t vKey = ((l >> 3) & 1) * 8 + (l & 7);
    uint32_t vDim = ((l >> 4) & 1) * 8;

    attn_stage(sbase,        kh, kl, vh, vl, gbase, 0,   tid); CP_COMMIT();
    attn_stage(sbase + ASTG, kh, kl, vh, vl, gbase, ACH, tid); CP_COMMIT();

    for (int c = 0; c < NCH; ++c) {
        CP_WAIT1();
        __syncthreads();
        uint32_t sb = sbase + (uint32_t)(c & 1) * ASTG;

        /* ---- scores ---- */
        float sacc[8][4];
#pragma unroll
        for (int j = 0; j < 8; ++j)
#pragma unroll
            for (int r = 0; r < 4; ++r) sacc[j][r] = 0.f;

#pragma unroll
        for (int kk = 0; kk < 4; ++kk) {
#pragma unroll
            for (int jp = 0; jp < 4; ++jp) {
                uint32_t off = (jp*16 + kKey)*VSTRB + (kk*16 + kDim)*2;
                uint32_t bh[4], bl[4];
                LDSM_X4(bh, sb + 0*ATILE + off);
                LDSM_X4(bl, sb + 1*ATILE + off);
                MMA16816(sacc[2*jp],   qhf[kk], bh + 0);
                MMA16816(sacc[2*jp],   qhf[kk], bl + 0);
                MMA16816(sacc[2*jp],   qlf[kk], bh + 0);
                MMA16816(sacc[2*jp+1], qhf[kk], bh + 2);
                MMA16816(sacc[2*jp+1], qhf[kk], bl + 2);
                MMA16816(sacc[2*jp+1], qlf[kk], bh + 2);
            }
        }

        /* ---- online softmax ---- */
        float cmA = -1e30f, cmB = -1e30f;
#pragma unroll
        for (int j = 0; j < 8; ++j) {
            cmA = fmaxf(cmA, fmaxf(sacc[j][0], sacc[j][1]));
            cmB = fmaxf(cmB, fmaxf(sacc[j][2], sacc[j][3]));
        }
        cmA = fmaxf(cmA, __shfl_xor_sync(0xffffffffu, cmA, 1));
        cmA = fmaxf(cmA, __shfl_xor_sync(0xffffffffu, cmA, 2));
        cmB = fmaxf(cmB, __shfl_xor_sync(0xffffffffu, cmB, 1));
        cmB = fmaxf(cmB, __shfl_xor_sync(0xffffffffu, cmB, 2));
        float nmA = fmaxf(mA, cmA), nmB = fmaxf(mB, cmB);
        float aA = __expf(mA - nmA), aB = __expf(mB - nmB);
        mA = nmA; mB = nmB;

        float sA = 0.f, sB = 0.f;
#pragma unroll
        for (int j = 0; j < 8; ++j) {
            sacc[j][0] = __expf(sacc[j][0] - nmA);
            sacc[j][1] = __expf(sacc[j][1] - nmA);
            sacc[j][2] = __expf(sacc[j][2] - nmB);
            sacc[j][3] = __expf(sacc[j][3] - nmB);
            sA += sacc[j][0] + sacc[j][1];
            sB += sacc[j][2] + sacc[j][3];
        }
        sA += __shfl_xor_sync(0xffffffffu, sA, 1);
        sA += __shfl_xor_sync(0xffffffffu, sA, 2);
        sB += __shfl_xor_sync(0xffffffffu, sB, 1);
        sB += __shfl_xor_sync(0xffffffffu, sB, 2);
        lA = lA*aA + sA;
        lB = lB*aB + sB;
#pragma unroll
        for (int j = 0; j < 8; ++j) {
            oacc[j][0] *= aA; oacc[j][1] *= aA;
            oacc[j][2] *= aB; oacc[j][3] *= aB;
        }

        /* ---- P·V ---- */
#pragma unroll
        for (int kk = 0; kk < 4; ++kk) {
            uint32_t ph[4], pl[4];
            split2(sacc[2*kk][0],   sacc[2*kk][1],   ph[0], pl[0]);
            split2(sacc[2*kk][2],   sacc[2*kk][3],   ph[1], pl[1]);
            split2(sacc[2*kk+1][0], sacc[2*kk+1][1], ph[2], pl[2]);
            split2(sacc[2*kk+1][2], sacc[2*kk+1][3], ph[3], pl[3]);
#pragma unroll
            for (int jp = 0; jp < 4; ++jp) {
                uint32_t off = (kk*16 + vKey)*VSTRB + (jp*16 + vDim)*2;
                uint32_t bh[4], bl[4];
                LDSM_X4T(bh, sb + 2*ATILE + off);
                LDSM_X4T(bl, sb + 3*ATILE + off);
                MMA16816(oacc[2*jp],   ph, bh + 0);
                MMA16816(oacc[2*jp],   ph, bl + 0);
                MMA16816(oacc[2*jp],   pl, bh + 0);
                MMA16816(oacc[2*jp+1], ph, bh + 2);
                MMA16816(oacc[2*jp+1], ph, bl + 2);
                MMA16816(oacc[2*jp+1], pl, bh + 2);
            }
        }

        __syncthreads();
        if (c + 2 < NCH)
            attn_stage(sbase + (uint32_t)(c & 1)*ASTG, kh, kl, vh, vl,
                       gbase, (c + 2)*ACH, tid);
        CP_COMMIT();
    }

    /* ---- epilogue ---- */
    float invA = 1.f / lA, invB = 1.f / lB;
    size_t rA = gbase + (size_t)qrow*DM;
#pragma unroll
    for (int j = 0; j < 8; ++j) {
        int col = j*8 + qcol;
        float2 o0, o1;
        o0.x = oacc[j][0]*invA; o0.y = oacc[j][1]*invA;
        o1.x = oacc[j][2]*invB; o1.y = oacc[j][3]*invB;
        *(float2*)&g_att[rA + col]         = o0;
        *(float2*)&g_att[rA + 8*DM + col]  = o1;
    }
}

/* ================= launch ================= */
extern "C" void kernel_launch(void* const* d_in, const int* in_sizes, int n_in,
                              void* d_out, int out_size)
{
    const float* x  = (const float*)d_in[0];
    const float* wq = (const float*)d_in[1];
    const float* bq = (const float*)d_in[2];
    const float* wk = (const float*)d_in[3];
    const float* bk = (const float*)d_in[4];
    const float* wv = (const float*)d_in[5];
    const float* bv = (const float*)d_in[6];
    const float* wo = (const float*)d_in[7];
    const float* bo = (const float*)d_in[8];
    float* out = (float*)d_out;

    float *gq, *gk, *gv, *ga;
    cudaGetSymbolAddress((void**)&gq, g_q);
    cudaGetSymbolAddress((void**)&gk, g_k);
    cudaGetSymbolAddress((void**)&gv, g_v);
    cudaGetSymbolAddress((void**)&ga, g_att);
    __nv_bfloat16 *xh, *xl, *ah, *al, *vh, *vl, *wh, *wl;
    cudaGetSymbolAddress((void**)&xh, g_xh);
    cudaGetSymbolAddress((void**)&xl, g_xl);
    cudaGetSymbolAddress((void**)&ah, g_ah);
    cudaGetSymbolAddress((void**)&al, g_al);
    cudaGetSymbolAddress((void**)&vh, g_vh);
    cudaGetSymbolAddress((void**)&vl, g_vl);
    cudaGetSymbolAddress((void**)&wh, g_wh);
    cudaGetSymbolAddress((void**)&wl, g_wl);

    cudaFuncSetAttribute(gemm_tc_kernel, cudaFuncAttributeMaxDynamicSharedMemorySize,
                         GEMM_SMEM);
    cudaFuncSetAttribute(attn_tc_kernel, cudaFuncAttributeMaxDynamicSharedMemorySize,
                         ATTN_SMEM);

    init_invfreq_kernel<<<1, 32>>>();

    const int n4x = TOK*DM/4;
    const int n4w = DM*DM/4;
    cvt_split_kernel<<<(n4x+255)/256, 256>>>(x,  xh, xl, n4x, 1.f);
    cvt_split_kernel<<<(n4w+255)/256, 256>>>(wq, wh + 0*(size_t)DM*DM, wl + 0*(size_t)DM*DM, n4w, 1.f);
    cvt_split_kernel<<<(n4w+255)/256, 256>>>(wk, wh + 1*(size_t)DM*DM, wl + 1*(size_t)DM*DM, n4w, 1.f);
    cvt_split_kernel<<<(n4w+255)/256, 256>>>(wv, wh + 2*(size_t)DM*DM, wl + 2*(size_t)DM*DM, n4w, 1.f);
    cvt_split_kernel<<<(n4w+255)/256, 256>>>(wo, wh + 3*(size_t)DM*DM, wl + 3*(size_t)DM*DM, n4w, 1.f);

    dim3 ggrid(DM/128, TOK/128);
    gemm_tc_kernel<<<ggrid, 256, GEMM_SMEM>>>(xh, xl, wh + 0*(size_t)DM*DM, wl + 0*(size_t)DM*DM, bq, gq);
    gemm_tc_kernel<<<ggrid, 256, GEMM_SMEM>>>(xh, xl, wh + 1*(size_t)DM*DM, wl + 1*(size_t)DM*DM, bk, gk);
    gemm_tc_kernel<<<ggrid, 256, GEMM_SMEM>>>(xh, xl, wh + 2*(size_t)DM*DM, wl + 2*(size_t)DM*DM, bv, gv);

    int rope_threads = 2 * TOK * NH * (HD/2);
    rope_kernel<<<(rope_threads + 255)/256, 256>>>();

    /* convert q (scaled by 1/sqrt(HD)), k, v to split bf16 */
    cvt_split_kernel<<<(n4x+255)/256, 256>>>(gq, xh, xl, n4x, 0.125f);
    cvt_split_kernel<<<(n4x+255)/256, 256>>>(gk, ah, al, n4x, 1.f);
    cvt_split_kernel<<<(n4x+255)/256, 256>>>(gv, vh, vl, n4x, 1.f);

    dim3 agrid(SEQ/128, NH, NB);    /* (16,16,4) */
    attn_tc_kernel<<<agrid, 256, ATTN_SMEM>>>(xh, xl, ah, al, vh, vl);

    cvt_split_kernel<<<(n4x+255)/256, 256>>>(ga, xh, xl, n4x, 1.f);
    gemm_tc_kernel<<<ggrid, 256, GEMM_SMEM>>>(xh, xl, wh + 3*(size_t)DM*DM, wl + 3*(size_t)DM*DM, bo, out);
}

// round 5
// speedup vs baseline: 3.4204x; 1.0381x over previous
#include <cuda_runtime.h>
#include <cuda_bf16.h>
#include <math.h>
#include <cstdint>

#define NB   4
#define SEQ  2048
#define NH   16
#define HD   64
#define DM   1024
#define TOK  (NB*SEQ)      /* 8192 tokens */

/* ---- scratch (device globals: allocation-free rule) ---- */
__device__ float g_invf[HD/2];

__device__ __align__(256) __nv_bfloat16 g_xh[(size_t)TOK*DM];
__device__ __align__(256) __nv_bfloat16 g_xl[(size_t)TOK*DM];
__device__ __align__(256) __nv_bfloat16 g_qh[(size_t)TOK*DM];
__device__ __align__(256) __nv_bfloat16 g_ql[(size_t)TOK*DM];
__device__ __align__(256) __nv_bfloat16 g_kh[(size_t)TOK*DM];
__device__ __align__(256) __nv_bfloat16 g_kl[(size_t)TOK*DM];
__device__ __align__(256) __nv_bfloat16 g_vh[(size_t)TOK*DM];
__device__ __align__(256) __nv_bfloat16 g_vl[(size_t)TOK*DM];
__device__ __align__(256) __nv_bfloat16 g_oh[(size_t)TOK*DM];
__device__ __align__(256) __nv_bfloat16 g_ol[(size_t)TOK*DM];
__device__ __align__(256) __nv_bfloat16 g_wh[4][(size_t)DM*DM];
__device__ __align__(256) __nv_bfloat16 g_wl[4][(size_t)DM*DM];

/* ======================= PTX helpers (base sm_103 features only) ======================= */
__device__ __forceinline__ uint32_t smem_u32(const void* p) {
    uint32_t a;
    asm("{ .reg .u64 t; cvta.to.shared.u64 t, %1; cvt.u32.u64 %0, t; }" : "=r"(a) : "l"(p));
    return a;
}
#define CP_ASYNC16(dst, src) \
    asm volatile("cp.async.cg.shared.global [%0], [%1], 16;" :: "r"(dst), "l"(src) : "memory")
#define CP_COMMIT() asm volatile("cp.async.commit_group;" ::: "memory")
#define CP_WAIT1()  asm volatile("cp.async.wait_group 1;" ::: "memory")

#define LDSM_X4(r, a) \
    asm volatile("ldmatrix.sync.aligned.m8n8.x4.shared.b16 {%0,%1,%2,%3}, [%4];" \
        : "=r"((r)[0]), "=r"((r)[1]), "=r"((r)[2]), "=r"((r)[3]) : "r"(a))
#define LDSM_X2(r, a) \
    asm volatile("ldmatrix.sync.aligned.m8n8.x2.shared.b16 {%0,%1}, [%2];" \
        : "=r"((r)[0]), "=r"((r)[1]) : "r"(a))
#define LDSM_X4T(r, a) \
    asm volatile("ldmatrix.sync.aligned.m8n8.x4.trans.shared.b16 {%0,%1,%2,%3}, [%4];" \
        : "=r"((r)[0]), "=r"((r)[1]), "=r"((r)[2]), "=r"((r)[3]) : "r"(a))

#define MMA16816(c, a, b) \
    asm volatile("mma.sync.aligned.m16n8k16.row.col.f32.bf16.bf16.f32 " \
        "{%0,%1,%2,%3},{%4,%5,%6,%7},{%8,%9},{%0,%1,%2,%3};" \
        : "+f"((c)[0]), "+f"((c)[1]), "+f"((c)[2]), "+f"((c)[3]) \
        : "r"((a)[0]), "r"((a)[1]), "r"((a)[2]), "r"((a)[3]), "r"((b)[0]), "r"((b)[1]))

__device__ __forceinline__ void split2(float f0, float f1, uint32_t& h, uint32_t& lo) {
    __nv_bfloat162 hh = __floats2bfloat162_rn(f0, f1);
    float g0 = __bfloat162float(hh.x);
    float g1 = __bfloat162float(hh.y);
    __nv_bfloat162 ll = __floats2bfloat162_rn(f0 - g0, f1 - g1);
    h  = *(uint32_t*)&hh;
    lo = *(uint32_t*)&ll;
}

/* ================= inv_freq init ================= */
__global__ void init_invfreq_kernel() {
    int i = threadIdx.x;
    if (i < HD/2) {
        double v = pow(10000.0, -(double)i / 32.0);
        g_invf[i] = (float)v;
    }
}

/* ================= fp32 -> bf16 hi/lo split ================= */
__global__ __launch_bounds__(256) void cvt_split_kernel(
    const float* __restrict__ src, __nv_bfloat16* __restrict__ hi,
    __nv_bfloat16* __restrict__ lo, int n4)
{
    int i = blockIdx.x * 256 + threadIdx.x;
    if (i >= n4) return;
    float4 v = ((const float4*)src)[i];
    uint32_t h0, l0, h1, l1;
    split2(v.x, v.y, h0, l0);
    split2(v.z, v.w, h1, l1);
    ((uint2*)hi)[i] = make_uint2(h0, h1);
    ((uint2*)lo)[i] = make_uint2(l0, l1);
}

/* ================= mma.sync split-bf16 GEMM with fused epilogue =================
   C = A @ W^T + bias.  modes: 0 = fp32 out; 1 = split-bf16 out;
   2 = RoPE + scale + split-bf16 out. */
#define KT      32
#define SROW    40
#define TILE_B  (128*SROW*2)
#define STAGE_B (4*TILE_B)
#define GEMM_SMEM (2*STAGE_B)
#define NSTAGE  (DM/KT)

__device__ __forceinline__ void stage_loads(
    uint32_t sb, const __nv_bfloat16* __restrict__ Ah,
    const __nv_bfloat16* __restrict__ Al,
    const __nv_bfloat16* __restrict__ Wh,
    const __nv_bfloat16* __restrict__ Wl,
    int bm, int bn, int k0, int tid)
{
    const __nv_bfloat16* srcs[4] = {Ah, Al, Wh, Wl};
    int row0s[4] = {bm, bm, bn, bn};
    int r = tid >> 2, seg = tid & 3;
#pragma unroll
    for (int t = 0; t < 4; ++t) {
        const __nv_bfloat16* src = srcs[t];
        int row0 = row0s[t];
#pragma unroll
        for (int half = 0; half < 2; ++half) {
            int row = half * 64 + r;
            uint32_t d = sb + t*TILE_B + row*(SROW*2) + seg*16;
            const void* g = src + (size_t)(row0 + row)*DM + k0 + seg*8;
            CP_ASYNC16(d, g);
        }
    }
}

__device__ __forceinline__ float2 rope_rot(float2 v, int row, int col) {
    int n    = row & (SEQ-1);
    int pair = (col & 63) >> 1;
    float ang = (float)n * g_invf[pair];
    float s, c;
    sincosf(ang, &s, &c);
    float2 o;
    o.x = v.x*c - v.y*s;
    o.y = v.x*s + v.y*c;
    return o;
}

__global__ __launch_bounds__(256)
void gemm_tc_kernel(const __nv_bfloat16* __restrict__ Ah,
                    const __nv_bfloat16* __restrict__ Al,
                    const __nv_bfloat16* __restrict__ Wh,
                    const __nv_bfloat16* __restrict__ Wl,
                    const float* __restrict__ bias,
                    float* __restrict__ Cf,
                    __nv_bfloat16* __restrict__ Ch,
                    __nv_bfloat16* __restrict__ Cl,
                    int mode, float scale)
{
    extern __shared__ __align__(128) char smem[];
    uint32_t sbase = smem_u32(smem);
    int tid = threadIdx.x;
    int l   = tid & 31;
    int wid = tid >> 5;
    int wm  = wid & 1;
    int wn  = wid >> 1;
    int bm  = blockIdx.y * 128;
    int bn  = blockIdx.x * 128;

    float acc[4][4][4];
#pragma unroll
    for (int i = 0; i < 4; ++i)
#pragma unroll
        for (int j = 0; j < 4; ++j)
#pragma unroll
            for (int r = 0; r < 4; ++r) acc[i][j][r] = 0.f;

    int rowA = wm*64 + (l & 15);
    int kA   = (l >> 4) * 8;
    int rowB = wn*32 + (l & 7);
    int kB   = ((l >> 3) & 1) * 8;

    stage_loads(sbase,           Ah, Al, Wh, Wl, bm, bn, 0,  tid); CP_COMMIT();
    stage_loads(sbase + STAGE_B, Ah, Al, Wh, Wl, bm, bn, KT, tid); CP_COMMIT();

    for (int s = 0; s < NSTAGE; ++s) {
        CP_WAIT1();
        __syncthreads();
        uint32_t sb = sbase + (uint32_t)(s & 1) * STAGE_B;

#pragma unroll
        for (int kk = 0; kk < 2; ++kk) {
            int kb = kk * 16;
            uint32_t ah[4][4], al[4][4], wh[4][2], wl[4][2];
#pragma unroll
            for (int i = 0; i < 4; ++i) {
                uint32_t ao = sb + (uint32_t)((rowA + i*16)*(SROW*2) + (kb + kA)*2);
                LDSM_X4(ah[i], ao + 0*TILE_B);
                LDSM_X4(al[i], ao + 1*TILE_B);
            }
#pragma unroll
            for (int j = 0; j < 4; ++j) {
                uint32_t bo = sb + (uint32_t)((rowB + j*8)*(SROW*2) + (kb + kB)*2);
                LDSM_X2(wh[j], bo + 2*TILE_B);
                LDSM_X2(wl[j], bo + 3*TILE_B);
            }
#pragma unroll
            for (int i = 0; i < 4; ++i)
#pragma unroll
                for (int j = 0; j < 4; ++j) {
                    MMA16816(acc[i][j], ah[i], wh[j]);
                    MMA16816(acc[i][j], ah[i], wl[j]);
                    MMA16816(acc[i][j], al[i], wh[j]);
                }
        }
        __syncthreads();
        if (s + 2 < NSTAGE)
            stage_loads(sbase + (uint32_t)(s & 1)*STAGE_B, Ah, Al, Wh, Wl,
                        bm, bn, (s + 2)*KT, tid);
        CP_COMMIT();
    }

    /* fused epilogue */
    int g   = l >> 2, tig = l & 3;
#pragma unroll
    for (int i = 0; i < 4; ++i) {
        int row = bm + wm*64 + i*16 + g;
#pragma unroll
        for (int j = 0; j < 4; ++j) {
            int col = bn + wn*32 + j*8 + tig*2;
            float2 bv = *(const float2*)&bias[col];
            float2 v0, v1;
            v0.x = acc[i][j][0] + bv.x;  v0.y = acc[i][j][1] + bv.y;
            v1.x = acc[i][j][2] + bv.x;  v1.y = acc[i][j][3] + bv.y;
            if (mode == 2) {
                v0 = rope_rot(v0, row,     col);
                v1 = rope_rot(v1, row + 8, col);
                v0.x *= scale; v0.y *= scale;
                v1.x *= scale; v1.y *= scale;
            }
            if (mode == 0) {
                *(float2*)&Cf[(size_t)row*DM + col]     = v0;
                *(float2*)&Cf[(size_t)(row+8)*DM + col] = v1;
            } else {
                uint32_t h0, l0, h1, l1;
                split2(v0.x, v0.y, h0, l0);
                split2(v1.x, v1.y, h1, l1);
                *(uint32_t*)&Ch[(size_t)row*DM + col]     = h0;
                *(uint32_t*)&Cl[(size_t)row*DM + col]     = l0;
                *(uint32_t*)&Ch[(size_t)(row+8)*DM + col] = h1;
                *(uint32_t*)&Cl[(size_t)(row+8)*DM + col] = l1;
            }
        }
    }
}

/* ================= Tensor-core flash attention ================= */
#define ACH   64
#define VSTR  72
#define VSTRB (VSTR*2)
#define ATILE (ACH*VSTRB)
#define ASTG  (4*ATILE)
#define ATTN_SMEM (2*ASTG)
#define NCH   (SEQ/ACH)

__device__ __forceinline__ void attn_stage(
    uint32_t sb, const __nv_bfloat16* kh, const __nv_bfloat16* kl,
    const __nv_bfloat16* vh, const __nv_bfloat16* vl,
    size_t gbase, int k0, int tid)
{
    const __nv_bfloat16* srcs[4] = {kh, kl, vh, vl};
#pragma unroll
    for (int u = tid; u < 2048; u += 256) {
        int t   = u >> 9;
        int row = (u >> 3) & 63;
        int seg = u & 7;
        uint32_t d = sb + t*ATILE + row*VSTRB + seg*16;
        const void* g = srcs[t] + gbase + (size_t)(k0 + row)*DM + seg*8;
        CP_ASYNC16(d, g);
    }
}

__global__ __launch_bounds__(256)
void attn_tc_kernel(const __nv_bfloat16* __restrict__ qh,
                    const __nv_bfloat16* __restrict__ ql,
                    const __nv_bfloat16* __restrict__ kh,
                    const __nv_bfloat16* __restrict__ kl,
                    const __nv_bfloat16* __restrict__ vh,
                    const __nv_bfloat16* __restrict__ vl,
                    __nv_bfloat16* __restrict__ oh,
                    __nv_bfloat16* __restrict__ ol)
{
    extern __shared__ __align__(128) char smem[];
    uint32_t sbase = smem_u32(smem);
    int tid = threadIdx.x;
    int l   = tid & 31;
    int w   = tid >> 5;
    int q0  = blockIdx.x * 128;
    int h   = blockIdx.y;
    int b   = blockIdx.z;

    size_t gbase = (size_t)b*SEQ*DM + (size_t)h*HD;

    int qrow = q0 + w*16 + (l >> 2);
    int qcol = (l & 3) * 2;
    uint32_t qhf[4][4], qlf[4][4];
#pragma unroll
    for (int kk = 0; kk < 4; ++kk) {
        size_t o00 = gbase + (size_t)qrow*DM + kk*16 + qcol;
        qhf[kk][0] = *(const uint32_t*)(qh + o00);
        qhf[kk][1] = *(const uint32_t*)(qh + o00 + 8*DM);
        qhf[kk][2] = *(const uint32_t*)(qh + o00 + 8);
        qhf[kk][3] = *(const uint32_t*)(qh + o00 + 8*DM + 8);
        qlf[kk][0] = *(const uint32_t*)(ql + o00);
        qlf[kk][1] = *(const uint32_t*)(ql + o00 + 8*DM);
        qlf[kk][2] = *(const uint32_t*)(ql + o00 + 8);
        qlf[kk][3] = *(const uint32_t*)(ql + o00 + 8*DM + 8);
    }

    float oacc[8][4];
#pragma unroll
    for (int j = 0; j < 8; ++j)
#pragma unroll
        for (int r = 0; r < 4; ++r) oacc[j][r] = 0.f;
    float mA = -1e30f, mB = -1e30f, lA = 0.f, lB = 0.f;

    uint32_t kKey = ((l >> 4) & 1) * 8 + (l & 7);
    uint32_t kDim = ((l >> 3) & 1) * 8;
    uint32_t vKey = ((l >> 3) & 1) * 8 + (l & 7);
    uint32_t vDim = ((l >> 4) & 1) * 8;

    attn_stage(sbase,        kh, kl, vh, vl, gbase, 0,   tid); CP_COMMIT();
    attn_stage(sbase + ASTG, kh, kl, vh, vl, gbase, ACH, tid); CP_COMMIT();

    for (int c = 0; c < NCH; ++c) {
        CP_WAIT1();
        __syncthreads();
        uint32_t sb = sbase + (uint32_t)(c & 1) * ASTG;

        float sacc[8][4];
#pragma unroll
        for (int j = 0; j < 8; ++j)
#pragma unroll
            for (int r = 0; r < 4; ++r) sacc[j][r] = 0.f;

#pragma unroll
        for (int kk = 0; kk < 4; ++kk) {
#pragma unroll
            for (int jp = 0; jp < 4; ++jp) {
                uint32_t off = (jp*16 + kKey)*VSTRB + (kk*16 + kDim)*2;
                uint32_t bh[4], bl[4];
                LDSM_X4(bh, sb + 0*ATILE + off);
                LDSM_X4(bl, sb + 1*ATILE + off);
                MMA16816(sacc[2*jp],   qhf[kk], bh + 0);
                MMA16816(sacc[2*jp],   qhf[kk], bl + 0);
                MMA16816(sacc[2*jp],   qlf[kk], bh + 0);
                MMA16816(sacc[2*jp+1], qhf[kk], bh + 2);
                MMA16816(sacc[2*jp+1], qhf[kk], bl + 2);
                MMA16816(sacc[2*jp+1], qlf[kk], bh + 2);
            }
        }

        float cmA = -1e30f, cmB = -1e30f;
#pragma unroll
        for (int j = 0; j < 8; ++j) {
            cmA = fmaxf(cmA, fmaxf(sacc[j][0], sacc[j][1]));
            cmB = fmaxf(cmB, fmaxf(sacc[j][2], sacc[j][3]));
        }
        cmA = fmaxf(cmA, __shfl_xor_sync(0xffffffffu, cmA, 1));
        cmA = fmaxf(cmA, __shfl_xor_sync(0xffffffffu, cmA, 2));
        cmB = fmaxf(cmB, __shfl_xor_sync(0xffffffffu, cmB, 1));
        cmB = fmaxf(cmB, __shfl_xor_sync(0xffffffffu, cmB, 2));
        float nmA = fmaxf(mA, cmA), nmB = fmaxf(mB, cmB);
        float aA = __expf(mA - nmA), aB = __expf(mB - nmB);
        mA = nmA; mB = nmB;

        float sA = 0.f, sB = 0.f;
#pragma unroll
        for (int j = 0; j < 8; ++j) {
            sacc[j][0] = __expf(sacc[j][0] - nmA);
            sacc[j][1] = __expf(sacc[j][1] - nmA);
            sacc[j][2] = __expf(sacc[j][2] - nmB);
            sacc[j][3] = __expf(sacc[j][3] - nmB);
            sA += sacc[j][0] + sacc[j][1];
            sB += sacc[j][2] + sacc[j][3];
        }
        sA += __shfl_xor_sync(0xffffffffu, sA, 1);
        sA += __shfl_xor_sync(0xffffffffu, sA, 2);
        sB += __shfl_xor_sync(0xffffffffu, sB, 1);
        sB += __shfl_xor_sync(0xffffffffu, sB, 2);
        lA = lA*aA + sA;
        lB = lB*aB + sB;
#pragma unroll
        for (int j = 0; j < 8; ++j) {
            oacc[j][0] *= aA; oacc[j][1] *= aA;
            oacc[j][2] *= aB; oacc[j][3] *= aB;
        }

#pragma unroll
        for (int kk = 0; kk < 4; ++kk) {
            uint32_t ph[4], pl[4];
            split2(sacc[2*kk][0],   sacc[2*kk][1],   ph[0], pl[0]);
            split2(sacc[2*kk][2],   sacc[2*kk][3],   ph[1], pl[1]);
            split2(sacc[2*kk+1][0], sacc[2*kk+1][1], ph[2], pl[2]);
            split2(sacc[2*kk+1][2], sacc[2*kk+1][3], ph[3], pl[3]);
#pragma unroll
            for (int jp = 0; jp < 4; ++jp) {
                uint32_t off = (kk*16 + vKey)*VSTRB + (jp*16 + vDim)*2;
                uint32_t bh[4], bl[4];
                LDSM_X4T(bh, sb + 2*ATILE + off);
                LDSM_X4T(bl, sb + 3*ATILE + off);
                MMA16816(oacc[2*jp],   ph, bh + 0);
                MMA16816(oacc[2*jp],   ph, bl + 0);
                MMA16816(oacc[2*jp],   pl, bh + 0);
                MMA16816(oacc[2*jp+1], ph, bh + 2);
                MMA16816(oacc[2*jp+1], ph, bl + 2);
                MMA16816(oacc[2*jp+1], pl, bh + 2);
            }
        }

        __syncthreads();
        if (c + 2 < NCH)
            attn_stage(sbase + (uint32_t)(c & 1)*ASTG, kh, kl, vh, vl,
                       gbase, (c + 2)*ACH, tid);
        CP_COMMIT();
    }

    /* epilogue: normalize + split-bf16 store */
    float invA = 1.f / lA, invB = 1.f / lB;
    size_t rA = gbase + (size_t)qrow*DM;
#pragma unroll
    for (int j = 0; j < 8; ++j) {
        int col = j*8 + qcol;
        uint32_t h0, l0, h1, l1;
        split2(oacc[j][0]*invA, oacc[j][1]*invA, h0, l0);
        split2(oacc[j][2]*invB, oacc[j][3]*invB, h1, l1);
        *(uint32_t*)&oh[rA + col]        = h0;
        *(uint32_t*)&ol[rA + col]        = l0;
        *(uint32_t*)&oh[rA + 8*DM + col] = h1;
        *(uint32_t*)&ol[rA + 8*DM + col] = l1;
    }
}

/* ================= launch ================= */
extern "C" void kernel_launch(void* const* d_in, const int* in_sizes, int n_in,
                              void* d_out, int out_size)
{
    const float* x  = (const float*)d_in[0];
    const float* wq = (const float*)d_in[1];
    const float* bq = (const float*)d_in[2];
    const float* wk = (const float*)d_in[3];
    const float* bk = (const float*)d_in[4];
    const float* wv = (const float*)d_in[5];
    const float* bv = (const float*)d_in[6];
    const float* wo = (const float*)d_in[7];
    const float* bo = (const float*)d_in[8];
    float* out = (float*)d_out;

    __nv_bfloat16 *xh, *xl, *qh, *ql, *kh, *kl, *vh, *vl, *oh, *ol, *wh, *wl;
    cudaGetSymbolAddress((void**)&xh, g_xh);
    cudaGetSymbolAddress((void**)&xl, g_xl);
    cudaGetSymbolAddress((void**)&qh, g_qh);
    cudaGetSymbolAddress((void**)&ql, g_ql);
    cudaGetSymbolAddress((void**)&kh, g_kh);
    cudaGetSymbolAddress((void**)&kl, g_kl);
    cudaGetSymbolAddress((void**)&vh, g_vh);
    cudaGetSymbolAddress((void**)&vl, g_vl);
    cudaGetSymbolAddress((void**)&oh, g_oh);
    cudaGetSymbolAddress((void**)&ol, g_ol);
    cudaGetSymbolAddress((void**)&wh, g_wh);
    cudaGetSymbolAddress((void**)&wl, g_wl);

    cudaFuncSetAttribute(gemm_tc_kernel, cudaFuncAttributeMaxDynamicSharedMemorySize,
                         GEMM_SMEM);
    cudaFuncSetAttribute(attn_tc_kernel, cudaFuncAttributeMaxDynamicSharedMemorySize,
                         ATTN_SMEM);

    init_invfreq_kernel<<<1, 32>>>();

    const int n4x = TOK*DM/4;
    const int n4w = DM*DM/4;
    cvt_split_kernel<<<(n4x+255)/256, 256>>>(x,  xh, xl, n4x);
    cvt_split_kernel<<<(n4w+255)/256, 256>>>(wq, wh + 0*(size_t)DM*DM, wl + 0*(size_t)DM*DM, n4w);
    cvt_split_kernel<<<(n4w+255)/256, 256>>>(wk, wh + 1*(size_t)DM*DM, wl + 1*(size_t)DM*DM, n4w);
    cvt_split_kernel<<<(n4w+255)/256, 256>>>(wv, wh + 2*(size_t)DM*DM, wl + 2*(size_t)DM*DM, n4w);
    cvt_split_kernel<<<(n4w+255)/256, 256>>>(wo, wh + 3*(size_t)DM*DM, wl + 3*(size_t)DM*DM, n4w);

    dim3 ggrid(DM/128, TOK/128);
    /* Q: rope + 1/sqrt(HD) scale, split out */
    gemm_tc_kernel<<<ggrid, 256, GEMM_SMEM>>>(xh, xl, wh + 0*(size_t)DM*DM, wl + 0*(size_t)DM*DM,
                                              bq, nullptr, qh, ql, 2, 0.125f);
    /* K: rope, split out */
    gemm_tc_kernel<<<ggrid, 256, GEMM_SMEM>>>(xh, xl, wh + 1*(size_t)DM*DM, wl + 1*(size_t)DM*DM,
                                              bk, nullptr, kh, kl, 2, 1.f);
    /* V: split out */
    gemm_tc_kernel<<<ggrid, 256, GEMM_SMEM>>>(xh, xl, wh + 2*(size_t)DM*DM, wl + 2*(size_t)DM*DM,
                                              bv, nullptr, vh, vl, 1, 1.f);

    dim3 agrid(SEQ/128, NH, NB);
    attn_tc_kernel<<<agrid, 256, ATTN_SMEM>>>(qh, ql, kh, kl, vh, vl, oh, ol);

    /* O-projection: fp32 out */
    gemm_tc_kernel<<<ggrid, 256, GEMM_SMEM>>>(oh, ol, wh + 3*(size_t)DM*DM, wl + 3*(size_t)DM*DM,
                                              bo, out, nullptr, nullptr, 0, 1.f);
}